// round 9
// baseline (speedup 1.0000x reference)
#include <cuda_runtime.h>
#include <cuda_bf16.h>
#include <cstdint>

#define HW      65536
#define NPIX    524288
#define THREADS 256
#define PX_CTA  256
#define NCTAS   (NPIX / PX_CTA)   // 2048

// ---- dynamic smem byte layout ----
#define SW_OFF  0          // float2[1365] pair-packed w2..w7 = 10920 B
#define B_OFF   10944      // w1 bf16 hi/lo: 2 * 64*272 = 34816 -> ends 45760
#define EX_OFF  45760      // per-warp exchange: 8 * 32px * 272B = 69632 -> ends 115392
#define SMEM_TOTAL 115392

#define B_PITCH 272
#define B_SPLIT 17408
#define EX_PITCH 272
#define EX_WARP 8704       // 32 * 272

// pair-packed weight offsets inside s_w (float2 units)
#define W2OFF 0
#define W3OFF 1024
#define W4OFF 1280
#define W5OFF 1344
#define W6OFF 1360
#define W7OFF 1364

__device__ __forceinline__ uint32_t smem_u32(const void* p) {
    uint32_t a;
    asm("{ .reg .u64 t; cvta.to.shared.u64 t, %1; cvt.u32.u64 %0, t; }" : "=r"(a) : "l"(p));
    return a;
}
__device__ __forceinline__ float2 ffma2(float2 a, float2 b, float2 c) {
    unsigned long long ra = reinterpret_cast<unsigned long long&>(a);
    unsigned long long rb = reinterpret_cast<unsigned long long&>(b);
    unsigned long long rc = reinterpret_cast<unsigned long long&>(c);
    unsigned long long rd;
    asm("fma.rn.f32x2 %0, %1, %2, %3;" : "=l"(rd) : "l"(ra), "l"(rb), "l"(rc));
    return reinterpret_cast<float2&>(rd);
}
__device__ __forceinline__ float2 leaky2(float2 v) {
    v.x = fmaxf(v.x, 0.01f * v.x);
    v.y = fmaxf(v.y, 0.01f * v.y);
    return v;
}
__device__ __forceinline__ void ldmx4(uint32_t* r, uint32_t addr) {
    asm volatile("ldmatrix.sync.aligned.m8n8.x4.shared.b16 {%0,%1,%2,%3}, [%4];"
                 : "=r"(r[0]), "=r"(r[1]), "=r"(r[2]), "=r"(r[3]) : "r"(addr));
}
__device__ __forceinline__ void mma16816(float* d, const uint32_t* a, uint32_t b0, uint32_t b1) {
    asm volatile("mma.sync.aligned.m16n8k16.row.col.f32.bf16.bf16.f32 "
                 "{%0,%1,%2,%3}, {%4,%5,%6,%7}, {%8,%9}, {%0,%1,%2,%3};"
                 : "+f"(d[0]), "+f"(d[1]), "+f"(d[2]), "+f"(d[3])
                 : "r"(a[0]), "r"(a[1]), "r"(a[2]), "r"(a[3]), "r"(b0), "r"(b1));
}
__device__ __forceinline__ void cvt_hilo(float a, float b, uint32_t& hi, uint32_t& lo) {
    __nv_bfloat162 h2 = __floats2bfloat162_rn(a, b);
    float2 hf = __bfloat1622float2(h2);
    __nv_bfloat162 l2 = __floats2bfloat162_rn(a - hf.x, b - hf.y);
    hi = reinterpret_cast<uint32_t&>(h2);
    lo = reinterpret_cast<uint32_t&>(l2);
}

__device__ __forceinline__ void stage_pairs(float2* dst, const float* __restrict__ w,
                                            int cout, int cin, int tid) {
    int npair = (cout / 2) * cin;
    for (int i = tid; i < npair; i += THREADS) {
        int o2 = i / cin;
        int c  = i - o2 * cin;
        dst[c * (cout / 2) + o2] = make_float2(w[(2 * o2) * cin + c], w[(2 * o2 + 1) * cin + c]);
    }
}

// Scalar layer for ONE pixel, channel-pair packed (R3-proven math).
template <int CIN, int COUT>
__device__ __forceinline__ void layerv(const float2* __restrict__ sw, const float2* in, float2* outv) {
    constexpr int O2 = COUT / 2;
#pragma unroll
    for (int o = 0; o < O2; ++o) outv[o] = make_float2(0.f, 0.f);
#pragma unroll
    for (int c2 = 0; c2 < CIN / 2; ++c2) {
        float2 v = in[c2];
#pragma unroll
        for (int h = 0; h < 2; ++h) {
            float s = h ? v.y : v.x;
            float2 d = make_float2(s, s);
            const float2* wr = sw + (2 * c2 + h) * O2;
            if constexpr ((O2 & 1) == 0) {
                const float4* w4 = reinterpret_cast<const float4*>(wr);
#pragma unroll
                for (int o4 = 0; o4 < O2 / 2; ++o4) {
                    float4 wp = w4[o4];
                    outv[2 * o4]     = ffma2(d, make_float2(wp.x, wp.y), outv[2 * o4]);
                    outv[2 * o4 + 1] = ffma2(d, make_float2(wp.z, wp.w), outv[2 * o4 + 1]);
                }
            } else {
#pragma unroll
                for (int o = 0; o < O2; ++o) outv[o] = ffma2(d, wr[o], outv[o]);
            }
        }
    }
}

__global__ __launch_bounds__(THREADS, 2)
void fused_mlp7_hmma_kernel(const float* __restrict__ x,
                            const float* __restrict__ w1, const float* __restrict__ w2,
                            const float* __restrict__ w3, const float* __restrict__ w4,
                            const float* __restrict__ w5, const float* __restrict__ w6,
                            const float* __restrict__ w7,
                            float* __restrict__ out) {
    extern __shared__ char sm[];
    float2* s_w = reinterpret_cast<float2*>(sm + SW_OFF);

    const int tid  = threadIdx.x;
    const int lane = tid & 31;
    const int warp = tid >> 5;

    const uint32_t smu = smem_u32(sm);
    const uint32_t Bh  = smu + B_OFF;

    // ---- stage w1 as bf16 hi/lo, [o][c], 272B pitch ----
    for (int i = tid; i < 64 * 128; i += THREADS) {
        int o = i >> 7, c = i & 127;
        float f = w1[i];
        __nv_bfloat16 h = __float2bfloat16_rn(f);
        __nv_bfloat16 l = __float2bfloat16_rn(f - __bfloat162float(h));
        char* ad = sm + B_OFF + o * B_PITCH + c * 2;
        *reinterpret_cast<uint16_t*>(ad)           = reinterpret_cast<uint16_t&>(h);
        *reinterpret_cast<uint16_t*>(ad + B_SPLIT) = reinterpret_cast<uint16_t&>(l);
    }
    stage_pairs(s_w + W2OFF, w2, 32, 64, tid);
    stage_pairs(s_w + W3OFF, w3, 16, 32, tid);
    stage_pairs(s_w + W4OFF, w4, 8, 16, tid);
    stage_pairs(s_w + W5OFF, w5, 4, 8, tid);
    stage_pairs(s_w + W6OFF, w6, 2, 4, tid);
    if (tid == 0) s_w[W7OFF] = make_float2(w7[0], w7[1]);
    __syncthreads();   // B + s_w ready; the ONLY block barrier

    // ---- this CTA's 256-px slab (always within one image) ----
    const int slab = blockIdx.x * PX_CTA;
    const float* xb = x + (size_t)(slab >> 16) * (128 * HW) + (slab & (HW - 1));

    const int fg = lane >> 2;          // fragment row (0..7)
    const int t2 = (lane & 3) * 2;     // fragment col pair base
    const int pxw = warp * 32;         // warp's 32-px tile
    const int lrow = (lane & 7) + ((lane >> 3) & 1) * 8;
    const int lchk = lane >> 4;

    // acc: 2 mb x 8 nb x 4 = 64 f32
    float acc[2][8][4];
#pragma unroll
    for (int mb = 0; mb < 2; ++mb)
#pragma unroll
        for (int nb = 0; nb < 8; ++nb)
#pragma unroll
            for (int r = 0; r < 4; ++r) acc[mb][nb][r] = 0.f;

    float xr[2][8];
#define LOAD_XR(kb_)                                                              \
    do {                                                                          \
        const float* cb0 = xb + (size_t)((kb_) * 16 + t2) * HW;                   \
        const float* cb1 = cb0 + HW;                                              \
        const float* cb8 = cb0 + (size_t)8 * HW;                                  \
        const float* cb9 = cb8 + HW;                                              \
        _Pragma("unroll")                                                         \
        for (int mb = 0; mb < 2; ++mb) {                                          \
            int p0 = pxw + mb * 16 + fg;                                          \
            xr[mb][0] = cb0[p0];     xr[mb][1] = cb1[p0];                         \
            xr[mb][2] = cb0[p0 + 8]; xr[mb][3] = cb1[p0 + 8];                     \
            xr[mb][4] = cb8[p0];     xr[mb][5] = cb9[p0];                         \
            xr[mb][6] = cb8[p0 + 8]; xr[mb][7] = cb9[p0 + 8];                     \
        }                                                                         \
    } while (0)

    LOAD_XR(0);

#pragma unroll
    for (int kb = 0; kb < 8; ++kb) {
        uint32_t AH[2][4], AL[2][4];
#pragma unroll
        for (int mb = 0; mb < 2; ++mb) {
            cvt_hilo(xr[mb][0], xr[mb][1], AH[mb][0], AL[mb][0]);
            cvt_hilo(xr[mb][2], xr[mb][3], AH[mb][1], AL[mb][1]);
            cvt_hilo(xr[mb][4], xr[mb][5], AH[mb][2], AL[mb][2]);
            cvt_hilo(xr[mb][6], xr[mb][7], AH[mb][3], AL[mb][3]);
        }
        if (kb < 7) LOAD_XR(kb + 1);   // prefetch next k-step

        // per-p B fragments (short live range keeps regs <= 2-CTA budget)
#pragma unroll
        for (int p = 0; p < 4; ++p) {
            uint32_t BHf[4], BLf[4];
            uint32_t bd = Bh + (uint32_t)(p * 16 + lrow) * B_PITCH + kb * 32 + lchk * 16;
            ldmx4(BHf, bd);
            ldmx4(BLf, bd + B_SPLIT);
#pragma unroll
            for (int mb = 0; mb < 2; ++mb) {
                mma16816(acc[mb][2 * p],     AH[mb], BHf[0], BHf[2]);
                mma16816(acc[mb][2 * p + 1], AH[mb], BHf[1], BHf[3]);
                mma16816(acc[mb][2 * p],     AL[mb], BHf[0], BHf[2]);
                mma16816(acc[mb][2 * p + 1], AL[mb], BHf[1], BHf[3]);
                mma16816(acc[mb][2 * p],     AH[mb], BLf[0], BLf[2]);
                mma16816(acc[mb][2 * p + 1], AH[mb], BLf[1], BLf[3]);
            }
        }
    }
#undef LOAD_XR

    // ---- per-warp exchange: D -> leaky -> warp-private smem (no block barrier) ----
    char* exw = sm + EX_OFF + warp * EX_WARP;
    {
        const int qr = lane >> 2, qc = lane & 3;
#pragma unroll
        for (int mb = 0; mb < 2; ++mb) {
            char* row0 = exw + (size_t)(mb * 16 + qr) * EX_PITCH;
            char* row1 = row0 + 8 * EX_PITCH;
#pragma unroll
            for (int nb = 0; nb < 8; ++nb) {
                int cb = (nb * 8 + qc * 2) * 4;
                *reinterpret_cast<float2*>(row0 + cb) =
                    leaky2(make_float2(acc[mb][nb][0], acc[mb][nb][1]));
                *reinterpret_cast<float2*>(row1 + cb) =
                    leaky2(make_float2(acc[mb][nb][2], acc[mb][nb][3]));
            }
        }
    }
    __syncwarp();

    // ---- layers 2..7: 1 px/thread (px = pxw + lane) ----
    float2 a0[32];
    {
        const float4* r0 = reinterpret_cast<const float4*>(exw + (size_t)lane * EX_PITCH);
#pragma unroll
        for (int j = 0; j < 16; ++j) {
            float4 q = r0[j];
            a0[2 * j]     = make_float2(q.x, q.y);
            a0[2 * j + 1] = make_float2(q.z, q.w);
        }
    }

    float2 a1[16];
    layerv<64, 32>(s_w + W2OFF, a0, a1);
#pragma unroll
    for (int o = 0; o < 16; ++o) a1[o] = leaky2(a1[o]);
    float2 a2[8];
    layerv<32, 16>(s_w + W3OFF, a1, a2);
#pragma unroll
    for (int o = 0; o < 8; ++o) a2[o] = leaky2(a2[o]);
    float2 a3[4];
    layerv<16, 8>(s_w + W4OFF, a2, a3);
#pragma unroll
    for (int o = 0; o < 4; ++o) a3[o] = leaky2(a3[o]);
    float2 a4[2];
    layerv<8, 4>(s_w + W5OFF, a3, a4);
#pragma unroll
    for (int o = 0; o < 2; ++o) a4[o] = leaky2(a4[o]);
    float2 a5[1];
    layerv<4, 2>(s_w + W6OFF, a4, a5);
    a5[0] = leaky2(a5[0]);

    float2 w7p = s_w[W7OFF];
    out[slab + pxw + lane] = fmaf(a5[0].x, w7p.x, a5[0].y * w7p.y);
}

extern "C" void kernel_launch(void* const* d_in, const int* in_sizes, int n_in,
                              void* d_out, int out_size) {
    const float* x  = (const float*)d_in[0];
    const float* w1 = (const float*)d_in[1];
    const float* w2 = (const float*)d_in[2];
    const float* w3 = (const float*)d_in[3];
    const float* w4 = (const float*)d_in[4];
    const float* w5 = (const float*)d_in[5];
    const float* w6 = (const float*)d_in[6];
    const float* w7 = (const float*)d_in[7];
    float* out = (float*)d_out;

    cudaFuncSetAttribute(fused_mlp7_hmma_kernel,
                         cudaFuncAttributeMaxDynamicSharedMemorySize, SMEM_TOTAL);
    fused_mlp7_hmma_kernel<<<NCTAS, THREADS, SMEM_TOTAL>>>(x, w1, w2, w3, w4, w5, w6, w7, out);
}

// round 10
// speedup vs baseline: 1.0201x; 1.0201x over previous
#include <cuda_runtime.h>
#include <cuda_bf16.h>
#include <cstdint>

#define HW      65536
#define NPIX    524288
#define THREADS 128
#define PX_CTA  256
#define NCTAS   (NPIX / PX_CTA)   // 2048

// ---- dynamic smem byte layout ----
#define SW_OFF  0          // float2[1365] pair-packed w2..w7 = 10920 B
#define B_OFF   10944      // w1 bf16 hi/lo: 2 * 64*272 = 34816 -> ends 45760
#define A0_OFF  45760      // layer-1 output f32: 256*272 = 69632 -> ends 115392
#define SMEM_TOTAL 115392

#define B_PITCH 272
#define B_SPLIT 17408
#define A0_PITCH 272

// pair-packed weight offsets inside s_w (float2 units)
#define W2OFF 0
#define W3OFF 1024
#define W4OFF 1280
#define W5OFF 1344
#define W6OFF 1360
#define W7OFF 1364

__device__ __forceinline__ uint32_t smem_u32(const void* p) {
    uint32_t a;
    asm("{ .reg .u64 t; cvta.to.shared.u64 t, %1; cvt.u32.u64 %0, t; }" : "=r"(a) : "l"(p));
    return a;
}
__device__ __forceinline__ float2 ffma2(float2 a, float2 b, float2 c) {
    unsigned long long ra = reinterpret_cast<unsigned long long&>(a);
    unsigned long long rb = reinterpret_cast<unsigned long long&>(b);
    unsigned long long rc = reinterpret_cast<unsigned long long&>(c);
    unsigned long long rd;
    asm("fma.rn.f32x2 %0, %1, %2, %3;" : "=l"(rd) : "l"(ra), "l"(rb), "l"(rc));
    return reinterpret_cast<float2&>(rd);
}
__device__ __forceinline__ float2 leaky2(float2 v) {
    v.x = fmaxf(v.x, 0.01f * v.x);
    v.y = fmaxf(v.y, 0.01f * v.y);
    return v;
}
__device__ __forceinline__ void ldmx4(uint32_t* r, uint32_t addr) {
    asm volatile("ldmatrix.sync.aligned.m8n8.x4.shared.b16 {%0,%1,%2,%3}, [%4];"
                 : "=r"(r[0]), "=r"(r[1]), "=r"(r[2]), "=r"(r[3]) : "r"(addr));
}
__device__ __forceinline__ void mma16816(float* d, const uint32_t* a, uint32_t b0, uint32_t b1) {
    asm volatile("mma.sync.aligned.m16n8k16.row.col.f32.bf16.bf16.f32 "
                 "{%0,%1,%2,%3}, {%4,%5,%6,%7}, {%8,%9}, {%0,%1,%2,%3};"
                 : "+f"(d[0]), "+f"(d[1]), "+f"(d[2]), "+f"(d[3])
                 : "r"(a[0]), "r"(a[1]), "r"(a[2]), "r"(a[3]), "r"(b0), "r"(b1));
}
__device__ __forceinline__ void cvt_hilo(float a, float b, uint32_t& hi, uint32_t& lo) {
    __nv_bfloat162 h2 = __floats2bfloat162_rn(a, b);
    float2 hf = __bfloat1622float2(h2);
    __nv_bfloat162 l2 = __floats2bfloat162_rn(a - hf.x, b - hf.y);
    hi = reinterpret_cast<uint32_t&>(h2);
    lo = reinterpret_cast<uint32_t&>(l2);
}

__device__ __forceinline__ void stage_pairs(float2* dst, const float* __restrict__ w,
                                            int cout, int cin, int tid) {
    int npair = (cout / 2) * cin;
    for (int i = tid; i < npair; i += THREADS) {
        int o2 = i / cin;
        int c  = i - o2 * cin;
        dst[c * (cout / 2) + o2] = make_float2(w[(2 * o2) * cin + c], w[(2 * o2 + 1) * cin + c]);
    }
}

// R3-proven scalar layer for 2 pixels, channel-pair packed.
template <int CIN, int COUT>
__device__ __forceinline__ void layer2px(const float2* __restrict__ sw,
                                         const float2* in0, const float2* in1,
                                         float2* acc0, float2* acc1) {
    constexpr int O2 = COUT / 2;
#pragma unroll
    for (int o = 0; o < O2; ++o) { acc0[o] = make_float2(0.f, 0.f); acc1[o] = make_float2(0.f, 0.f); }
#pragma unroll
    for (int c2 = 0; c2 < CIN / 2; ++c2) {
        float2 v0 = in0[c2];
        float2 v1 = in1[c2];
#pragma unroll
        for (int h = 0; h < 2; ++h) {
            float s0 = h ? v0.y : v0.x;
            float s1 = h ? v1.y : v1.x;
            float2 d0 = make_float2(s0, s0);
            float2 d1 = make_float2(s1, s1);
            const float2* wr = sw + (2 * c2 + h) * O2;
            if constexpr ((O2 & 1) == 0) {
                const float4* w4 = reinterpret_cast<const float4*>(wr);
#pragma unroll
                for (int o4 = 0; o4 < O2 / 2; ++o4) {
                    float4 wp = w4[o4];
                    acc0[2 * o4]     = ffma2(d0, make_float2(wp.x, wp.y), acc0[2 * o4]);
                    acc1[2 * o4]     = ffma2(d1, make_float2(wp.x, wp.y), acc1[2 * o4]);
                    acc0[2 * o4 + 1] = ffma2(d0, make_float2(wp.z, wp.w), acc0[2 * o4 + 1]);
                    acc1[2 * o4 + 1] = ffma2(d1, make_float2(wp.z, wp.w), acc1[2 * o4 + 1]);
                }
            } else {
#pragma unroll
                for (int o = 0; o < O2; ++o) {
                    float2 wp = wr[o];
                    acc0[o] = ffma2(d0, wp, acc0[o]);
                    acc1[o] = ffma2(d1, wp, acc1[o]);
                }
            }
        }
    }
}

__global__ __launch_bounds__(THREADS, 2)
void fused_mlp7_hmma_kernel(const float* __restrict__ x,
                            const float* __restrict__ w1, const float* __restrict__ w2,
                            const float* __restrict__ w3, const float* __restrict__ w4,
                            const float* __restrict__ w5, const float* __restrict__ w6,
                            const float* __restrict__ w7,
                            float* __restrict__ out) {
    extern __shared__ char sm[];
    float2* s_w = reinterpret_cast<float2*>(sm + SW_OFF);

    const int tid  = threadIdx.x;
    const int lane = tid & 31;
    const int warp = tid >> 5;          // 0..3

    const uint32_t smu = smem_u32(sm);
    const uint32_t Bh  = smu + B_OFF;

    // ---- stage w1 as bf16 hi/lo, [o][c], 272B pitch ----
    for (int i = tid; i < 64 * 128; i += THREADS) {
        int o = i >> 7, c = i & 127;
        float f = w1[i];
        __nv_bfloat16 h = __float2bfloat16_rn(f);
        __nv_bfloat16 l = __float2bfloat16_rn(f - __bfloat162float(h));
        char* ad = sm + B_OFF + o * B_PITCH + c * 2;
        *reinterpret_cast<uint16_t*>(ad)           = reinterpret_cast<uint16_t&>(h);
        *reinterpret_cast<uint16_t*>(ad + B_SPLIT) = reinterpret_cast<uint16_t&>(l);
    }
    stage_pairs(s_w + W2OFF, w2, 32, 64, tid);
    stage_pairs(s_w + W3OFF, w3, 16, 32, tid);
    stage_pairs(s_w + W4OFF, w4, 8, 16, tid);
    stage_pairs(s_w + W5OFF, w5, 4, 8, tid);
    stage_pairs(s_w + W6OFF, w6, 2, 4, tid);
    if (tid == 0) s_w[W7OFF] = make_float2(w7[0], w7[1]);
    __syncthreads();   // B + s_w ready

    // ---- this CTA's 256-px slab (always within one image) ----
    const int slab = blockIdx.x * PX_CTA;
    const float* xb = x + (size_t)(slab >> 16) * (128 * HW) + (slab & (HW - 1));

    const int fg = lane >> 2;          // fragment row (0..7)
    const int t2 = (lane & 3) * 2;     // fragment col pair base
    const int pxw = warp * 64;         // warp's 64-px tile
    const int lrow = (lane & 7) + ((lane >> 3) & 1) * 8;
    const int lchk = lane >> 4;

    // acc: 4 mb x 8 nb x 4 = 128 f32 (R8 tile)
    float acc[4][8][4];
#pragma unroll
    for (int mb = 0; mb < 4; ++mb)
#pragma unroll
        for (int nb = 0; nb < 8; ++nb)
#pragma unroll
            for (int r = 0; r < 4; ++r) acc[mb][nb][r] = 0.f;

    float xr[4][8];
#define LOAD_XR(kb_)                                                              \
    do {                                                                          \
        const float* cb0 = xb + (size_t)((kb_) * 16 + t2) * HW;                   \
        const float* cb1 = cb0 + HW;                                              \
        const float* cb8 = cb0 + (size_t)8 * HW;                                  \
        const float* cb9 = cb8 + HW;                                              \
        _Pragma("unroll")                                                         \
        for (int mb = 0; mb < 4; ++mb) {                                          \
            int p0 = pxw + mb * 16 + fg;                                          \
            xr[mb][0] = cb0[p0];     xr[mb][1] = cb1[p0];                         \
            xr[mb][2] = cb0[p0 + 8]; xr[mb][3] = cb1[p0 + 8];                     \
            xr[mb][4] = cb8[p0];     xr[mb][5] = cb9[p0];                         \
            xr[mb][6] = cb8[p0 + 8]; xr[mb][7] = cb9[p0 + 8];                     \
        }                                                                         \
    } while (0)

    LOAD_XR(0);

#pragma unroll
    for (int kb = 0; kb < 8; ++kb) {
        uint32_t AH[4][4], AL[4][4];
#pragma unroll
        for (int mb = 0; mb < 4; ++mb) {
            cvt_hilo(xr[mb][0], xr[mb][1], AH[mb][0], AL[mb][0]);
            cvt_hilo(xr[mb][2], xr[mb][3], AH[mb][1], AL[mb][1]);
            cvt_hilo(xr[mb][4], xr[mb][5], AH[mb][2], AL[mb][2]);
            cvt_hilo(xr[mb][6], xr[mb][7], AH[mb][3], AL[mb][3]);
        }
        if (kb < 7) LOAD_XR(kb + 1);   // prefetch next k-step

        // per-p B fragments, amortized over 4 mb
#pragma unroll
        for (int p = 0; p < 4; ++p) {
            uint32_t BHf[4], BLf[4];
            uint32_t bd = Bh + (uint32_t)(p * 16 + lrow) * B_PITCH + kb * 32 + lchk * 16;
            ldmx4(BHf, bd);
            ldmx4(BLf, bd + B_SPLIT);
#pragma unroll
            for (int mb = 0; mb < 4; ++mb) {
                mma16816(acc[mb][2 * p],     AH[mb], BHf[0], BHf[2]);
                mma16816(acc[mb][2 * p + 1], AH[mb], BHf[1], BHf[3]);
                mma16816(acc[mb][2 * p],     AL[mb], BHf[0], BHf[2]);
                mma16816(acc[mb][2 * p + 1], AL[mb], BHf[1], BHf[3]);
                mma16816(acc[mb][2 * p],     AH[mb], BLf[0], BLf[2]);
                mma16816(acc[mb][2 * p + 1], AH[mb], BLf[1], BLf[3]);
            }
        }
    }
#undef LOAD_XR

    // ---- D fragments -> leaky -> a0[px][o] (272B pitch) ----
    {
        const int qr = lane >> 2, qc = lane & 3;
#pragma unroll
        for (int mb = 0; mb < 4; ++mb) {
            int px = pxw + mb * 16 + qr;
            char* row0 = sm + A0_OFF + (size_t)px * A0_PITCH;
            char* row1 = row0 + 8 * A0_PITCH;
#pragma unroll
            for (int nb = 0; nb < 8; ++nb) {
                int cb = (nb * 8 + qc * 2) * 4;
                *reinterpret_cast<float2*>(row0 + cb) =
                    leaky2(make_float2(acc[mb][nb][0], acc[mb][nb][1]));
                *reinterpret_cast<float2*>(row1 + cb) =
                    leaky2(make_float2(acc[mb][nb][2], acc[mb][nb][3]));
            }
        }
    }
    __syncthreads();

    // ---- layers 2..7, 2 px/thread (rows tid, tid+128) ----
    float2 a0_0[32], a0_1[32];
    {
        const float4* r0 = reinterpret_cast<const float4*>(sm + A0_OFF + (size_t)tid * A0_PITCH);
        const float4* r1 = reinterpret_cast<const float4*>(sm + A0_OFF + (size_t)(tid + 128) * A0_PITCH);
#pragma unroll
        for (int j = 0; j < 16; ++j) {
            float4 q0 = r0[j], q1 = r1[j];
            a0_0[2 * j]     = make_float2(q0.x, q0.y);
            a0_0[2 * j + 1] = make_float2(q0.z, q0.w);
            a0_1[2 * j]     = make_float2(q1.x, q1.y);
            a0_1[2 * j + 1] = make_float2(q1.z, q1.w);
        }
    }

    float2 a1_0[16], a1_1[16];
    layer2px<64, 32>(s_w + W2OFF, a0_0, a0_1, a1_0, a1_1);
#pragma unroll
    for (int o = 0; o < 16; ++o) { a1_0[o] = leaky2(a1_0[o]); a1_1[o] = leaky2(a1_1[o]); }

    float2 a2_0[8], a2_1[8];
    layer2px<32, 16>(s_w + W3OFF, a1_0, a1_1, a2_0, a2_1);
#pragma unroll
    for (int o = 0; o < 8; ++o) { a2_0[o] = leaky2(a2_0[o]); a2_1[o] = leaky2(a2_1[o]); }

    float2 a3_0[4], a3_1[4];
    layer2px<16, 8>(s_w + W4OFF, a2_0, a2_1, a3_0, a3_1);
#pragma unroll
    for (int o = 0; o < 4; ++o) { a3_0[o] = leaky2(a3_0[o]); a3_1[o] = leaky2(a3_1[o]); }

    float2 a4_0[2], a4_1[2];
    layer2px<8, 4>(s_w + W5OFF, a3_0, a3_1, a4_0, a4_1);
#pragma unroll
    for (int o = 0; o < 2; ++o) { a4_0[o] = leaky2(a4_0[o]); a4_1[o] = leaky2(a4_1[o]); }

    float2 a5_0[1], a5_1[1];
    layer2px<4, 2>(s_w + W6OFF, a4_0, a4_1, a5_0, a5_1);
    a5_0[0] = leaky2(a5_0[0]);
    a5_1[0] = leaky2(a5_1[0]);

    float2 w7p = s_w[W7OFF];
    out[slab + tid]       = fmaf(a5_0[0].x, w7p.x, a5_0[0].y * w7p.y);
    out[slab + tid + 128] = fmaf(a5_1[0].x, w7p.x, a5_1[0].y * w7p.y);
}

extern "C" void kernel_launch(void* const* d_in, const int* in_sizes, int n_in,
                              void* d_out, int out_size) {
    const float* x  = (const float*)d_in[0];
    const float* w1 = (const float*)d_in[1];
    const float* w2 = (const float*)d_in[2];
    const float* w3 = (const float*)d_in[3];
    const float* w4 = (const float*)d_in[4];
    const float* w5 = (const float*)d_in[5];
    const float* w6 = (const float*)d_in[6];
    const float* w7 = (const float*)d_in[7];
    float* out = (float*)d_out;

    cudaFuncSetAttribute(fused_mlp7_hmma_kernel,
                         cudaFuncAttributeMaxDynamicSharedMemorySize, SMEM_TOTAL);
    fused_mlp7_hmma_kernel<<<NCTAS, THREADS, SMEM_TOTAL>>>(x, w1, w2, w3, w4, w5, w6, w7, out);
}

// round 11
// speedup vs baseline: 1.1784x; 1.1551x over previous
#include <cuda_runtime.h>
#include <cuda_bf16.h>
#include <cstdint>

#define HW      65536
#define NPIX    524288
#define THREADS 256
#define PX_CTA  512
#define NCTAS   (NPIX / PX_CTA)   // 1024

// ---- dynamic smem byte layout ----
#define SW_OFF  0          // float2[341] pair-packed w3..w7 = 2728 -> pad 2752
#define B1_OFF  2752       // w1 bf16 hi/lo: 2 * 64*272 = 34816 -> ends 37568
#define B2_OFF  37568      // w2 bf16 hi/lo: 2 * 32*144 = 9216  -> ends 46784
#define EX_OFF  46784      // a1 exchange [c2][px]: 16 * 512 * 8 = 65536 -> ends 112320
#define SMEM_TOTAL 112320

#define B1_PITCH 272
#define B1_SPLIT 17408     // 64*272
#define B2_PITCH 144
#define B2_SPLIT 4608      // 32*144

// pair-packed weight offsets inside s_w (float2 units)
#define W3OFF 0            // 32c x 8  = 256
#define W4OFF 256          // 16c x 4  = 64
#define W5OFF 320          // 8c  x 2  = 16
#define W6OFF 336          // 4c  x 1  = 4
#define W7OFF 340

__device__ __forceinline__ uint32_t smem_u32(const void* p) {
    uint32_t a;
    asm("{ .reg .u64 t; cvta.to.shared.u64 t, %1; cvt.u32.u64 %0, t; }" : "=r"(a) : "l"(p));
    return a;
}
__device__ __forceinline__ float2 ffma2(float2 a, float2 b, float2 c) {
    unsigned long long ra = reinterpret_cast<unsigned long long&>(a);
    unsigned long long rb = reinterpret_cast<unsigned long long&>(b);
    unsigned long long rc = reinterpret_cast<unsigned long long&>(c);
    unsigned long long rd;
    asm("fma.rn.f32x2 %0, %1, %2, %3;" : "=l"(rd) : "l"(ra), "l"(rb), "l"(rc));
    return reinterpret_cast<float2&>(rd);
}
__device__ __forceinline__ float2 leaky2(float2 v) {
    v.x = fmaxf(v.x, 0.01f * v.x);
    v.y = fmaxf(v.y, 0.01f * v.y);
    return v;
}
__device__ __forceinline__ void ldmx4(uint32_t* r, uint32_t addr) {
    asm volatile("ldmatrix.sync.aligned.m8n8.x4.shared.b16 {%0,%1,%2,%3}, [%4];"
                 : "=r"(r[0]), "=r"(r[1]), "=r"(r[2]), "=r"(r[3]) : "r"(addr));
}
__device__ __forceinline__ void mma16816(float* d, const uint32_t* a, uint32_t b0, uint32_t b1) {
    asm volatile("mma.sync.aligned.m16n8k16.row.col.f32.bf16.bf16.f32 "
                 "{%0,%1,%2,%3}, {%4,%5,%6,%7}, {%8,%9}, {%0,%1,%2,%3};"
                 : "+f"(d[0]), "+f"(d[1]), "+f"(d[2]), "+f"(d[3])
                 : "r"(a[0]), "r"(a[1]), "r"(a[2]), "r"(a[3]), "r"(b0), "r"(b1));
}
__device__ __forceinline__ void cvt_hilo(float a, float b, uint32_t& hi, uint32_t& lo) {
    __nv_bfloat162 h2 = __floats2bfloat162_rn(a, b);
    float2 hf = __bfloat1622float2(h2);
    __nv_bfloat162 l2 = __floats2bfloat162_rn(a - hf.x, b - hf.y);
    hi = reinterpret_cast<uint32_t&>(h2);
    lo = reinterpret_cast<uint32_t&>(l2);
}

__device__ __forceinline__ void stage_pairs(float2* dst, const float* __restrict__ w,
                                            int cout, int cin, int tid) {
    int npair = (cout / 2) * cin;
    for (int i = tid; i < npair; i += THREADS) {
        int o2 = i / cin;
        int c  = i - o2 * cin;
        dst[c * (cout / 2) + o2] = make_float2(w[(2 * o2) * cin + c], w[(2 * o2 + 1) * cin + c]);
    }
}

// stage weight [cout][cin] as bf16 hi/lo rows with given pitch/split
__device__ __forceinline__ void stage_bf16(char* base, uint32_t pitch, uint32_t split,
                                           const float* __restrict__ w, int cout, int cin, int tid) {
    for (int i = tid; i < cout * cin; i += THREADS) {
        int o = i / cin, c = i - o * cin;
        float f = w[i];
        __nv_bfloat16 h = __float2bfloat16_rn(f);
        __nv_bfloat16 l = __float2bfloat16_rn(f - __bfloat162float(h));
        char* ad = base + o * pitch + c * 2;
        *reinterpret_cast<uint16_t*>(ad)         = reinterpret_cast<uint16_t&>(h);
        *reinterpret_cast<uint16_t*>(ad + split) = reinterpret_cast<uint16_t&>(l);
    }
}

// R3-proven scalar layer for 2 pixels, channel-pair packed.
template <int CIN, int COUT>
__device__ __forceinline__ void layer2px(const float2* __restrict__ sw,
                                         const float2* in0, const float2* in1,
                                         float2* acc0, float2* acc1) {
    constexpr int O2 = COUT / 2;
#pragma unroll
    for (int o = 0; o < O2; ++o) { acc0[o] = make_float2(0.f, 0.f); acc1[o] = make_float2(0.f, 0.f); }
#pragma unroll
    for (int c2 = 0; c2 < CIN / 2; ++c2) {
        float2 v0 = in0[c2];
        float2 v1 = in1[c2];
#pragma unroll
        for (int h = 0; h < 2; ++h) {
            float s0 = h ? v0.y : v0.x;
            float s1 = h ? v1.y : v1.x;
            float2 d0 = make_float2(s0, s0);
            float2 d1 = make_float2(s1, s1);
            const float2* wr = sw + (2 * c2 + h) * O2;
            if constexpr ((O2 & 3) == 0) {
                const float4* w4 = reinterpret_cast<const float4*>(wr);
#pragma unroll
                for (int o4 = 0; o4 < O2 / 2; ++o4) {
                    float4 wp = w4[o4];
                    acc0[2 * o4]     = ffma2(d0, make_float2(wp.x, wp.y), acc0[2 * o4]);
                    acc1[2 * o4]     = ffma2(d1, make_float2(wp.x, wp.y), acc1[2 * o4]);
                    acc0[2 * o4 + 1] = ffma2(d0, make_float2(wp.z, wp.w), acc0[2 * o4 + 1]);
                    acc1[2 * o4 + 1] = ffma2(d1, make_float2(wp.z, wp.w), acc1[2 * o4 + 1]);
                }
            } else {
#pragma unroll
                for (int o = 0; o < O2; ++o) {
                    float2 wp = wr[o];
                    acc0[o] = ffma2(d0, wp, acc0[o]);
                    acc1[o] = ffma2(d1, wp, acc1[o]);
                }
            }
        }
    }
}

__global__ __launch_bounds__(THREADS, 1)
void fused_mlp7_hmma2_kernel(const float* __restrict__ x,
                             const float* __restrict__ w1, const float* __restrict__ w2,
                             const float* __restrict__ w3, const float* __restrict__ w4,
                             const float* __restrict__ w5, const float* __restrict__ w6,
                             const float* __restrict__ w7,
                             float* __restrict__ out) {
    extern __shared__ char sm[];
    float2* s_w   = reinterpret_cast<float2*>(sm + SW_OFF);
    float2* ex_f2 = reinterpret_cast<float2*>(sm + EX_OFF);

    const int tid  = threadIdx.x;
    const int lane = tid & 31;
    const int warp = tid >> 5;          // 0..7

    const uint32_t smu = smem_u32(sm);
    const uint32_t B1h = smu + B1_OFF;
    const uint32_t B2h = smu + B2_OFF;

    stage_bf16(sm + B1_OFF, B1_PITCH, B1_SPLIT, w1, 64, 128, tid);
    stage_bf16(sm + B2_OFF, B2_PITCH, B2_SPLIT, w2, 32, 64, tid);
    stage_pairs(s_w + W3OFF, w3, 16, 32, tid);
    stage_pairs(s_w + W4OFF, w4, 8, 16, tid);
    stage_pairs(s_w + W5OFF, w5, 4, 8, tid);
    stage_pairs(s_w + W6OFF, w6, 2, 4, tid);
    if (tid == 0) s_w[W7OFF] = make_float2(w7[0], w7[1]);
    __syncthreads();

    // ---- this CTA's 512-px slab (always within one image) ----
    const int slab = blockIdx.x * PX_CTA;
    const float* xb = x + (size_t)(slab >> 16) * (128 * HW) + (slab & (HW - 1));

    const int fg = lane >> 2;          // fragment row group (0..7)
    const int t2 = (lane & 3) * 2;     // fragment col pair base
    const int pxw = warp * 64;         // warp's 64-px tile
    const int lrow = (lane & 7) + ((lane >> 3) & 1) * 8;
    const int lchk = lane >> 4;

    // ================= Layer 1: MMA 64px x 64o x K128 =================
    float acc[4][8][4];
#pragma unroll
    for (int mb = 0; mb < 4; ++mb)
#pragma unroll
        for (int nb = 0; nb < 8; ++nb)
#pragma unroll
            for (int r = 0; r < 4; ++r) acc[mb][nb][r] = 0.f;

    float xr[4][8];
#define LOAD_XR(kb_)                                                              \
    do {                                                                          \
        const float* cb0 = xb + (size_t)((kb_) * 16 + t2) * HW;                   \
        const float* cb1 = cb0 + HW;                                              \
        const float* cb8 = cb0 + (size_t)8 * HW;                                  \
        const float* cb9 = cb8 + HW;                                              \
        _Pragma("unroll")                                                         \
        for (int mb = 0; mb < 4; ++mb) {                                          \
            int p0 = pxw + mb * 16 + fg;                                          \
            xr[mb][0] = cb0[p0];     xr[mb][1] = cb1[p0];                         \
            xr[mb][2] = cb0[p0 + 8]; xr[mb][3] = cb1[p0 + 8];                     \
            xr[mb][4] = cb8[p0];     xr[mb][5] = cb9[p0];                         \
            xr[mb][6] = cb8[p0 + 8]; xr[mb][7] = cb9[p0 + 8];                     \
        }                                                                         \
    } while (0)

    LOAD_XR(0);

#pragma unroll
    for (int kb = 0; kb < 8; ++kb) {
        uint32_t AH[4][4], AL[4][4];
#pragma unroll
        for (int mb = 0; mb < 4; ++mb) {
            cvt_hilo(xr[mb][0], xr[mb][1], AH[mb][0], AL[mb][0]);
            cvt_hilo(xr[mb][2], xr[mb][3], AH[mb][1], AL[mb][1]);
            cvt_hilo(xr[mb][4], xr[mb][5], AH[mb][2], AL[mb][2]);
            cvt_hilo(xr[mb][6], xr[mb][7], AH[mb][3], AL[mb][3]);
        }
        if (kb < 7) LOAD_XR(kb + 1);

#pragma unroll
        for (int p = 0; p < 4; ++p) {
            uint32_t BHf[4], BLf[4];
            uint32_t bd = B1h + (uint32_t)(p * 16 + lrow) * B1_PITCH + kb * 32 + lchk * 16;
            ldmx4(BHf, bd);
            ldmx4(BLf, bd + B1_SPLIT);
            // chain-major: same-acc reuse distance = 8 MMAs
#pragma unroll
            for (int mb = 0; mb < 4; ++mb) {
                mma16816(acc[mb][2 * p],     AH[mb], BHf[0], BHf[2]);
                mma16816(acc[mb][2 * p + 1], AH[mb], BHf[1], BHf[3]);
            }
#pragma unroll
            for (int mb = 0; mb < 4; ++mb) {
                mma16816(acc[mb][2 * p],     AL[mb], BHf[0], BHf[2]);
                mma16816(acc[mb][2 * p + 1], AL[mb], BHf[1], BHf[3]);
            }
#pragma unroll
            for (int mb = 0; mb < 4; ++mb) {
                mma16816(acc[mb][2 * p],     AH[mb], BLf[0], BLf[2]);
                mma16816(acc[mb][2 * p + 1], AH[mb], BLf[1], BLf[3]);
            }
        }
    }
#undef LOAD_XR

    // ================= Layer 2: MMA 64px x 32o x K64, A from D fragments =================
    float acc2[4][4][4];
#pragma unroll
    for (int mb = 0; mb < 4; ++mb)
#pragma unroll
        for (int nb = 0; nb < 4; ++nb)
#pragma unroll
            for (int r = 0; r < 4; ++r) acc2[mb][nb][r] = 0.f;

#pragma unroll
    for (int kb2 = 0; kb2 < 4; ++kb2) {
        // A2 fragments: leaky(D) -> bf16 hi/lo, straight from acc registers
        uint32_t A2H[4][4], A2L[4][4];
#pragma unroll
        for (int mb = 0; mb < 4; ++mb) {
            float2 v0 = leaky2(make_float2(acc[mb][2 * kb2][0],     acc[mb][2 * kb2][1]));
            float2 v1 = leaky2(make_float2(acc[mb][2 * kb2][2],     acc[mb][2 * kb2][3]));
            float2 v2 = leaky2(make_float2(acc[mb][2 * kb2 + 1][0], acc[mb][2 * kb2 + 1][1]));
            float2 v3 = leaky2(make_float2(acc[mb][2 * kb2 + 1][2], acc[mb][2 * kb2 + 1][3]));
            cvt_hilo(v0.x, v0.y, A2H[mb][0], A2L[mb][0]);
            cvt_hilo(v1.x, v1.y, A2H[mb][1], A2L[mb][1]);
            cvt_hilo(v2.x, v2.y, A2H[mb][2], A2L[mb][2]);
            cvt_hilo(v3.x, v3.y, A2H[mb][3], A2L[mb][3]);
        }
#pragma unroll
        for (int p2 = 0; p2 < 2; ++p2) {
            uint32_t BHf[4], BLf[4];
            uint32_t bd = B2h + (uint32_t)(p2 * 16 + lrow) * B2_PITCH + kb2 * 32 + lchk * 16;
            ldmx4(BHf, bd);
            ldmx4(BLf, bd + B2_SPLIT);
#pragma unroll
            for (int mb = 0; mb < 4; ++mb) {
                mma16816(acc2[mb][2 * p2],     A2H[mb], BHf[0], BHf[2]);
                mma16816(acc2[mb][2 * p2 + 1], A2H[mb], BHf[1], BHf[3]);
            }
#pragma unroll
            for (int mb = 0; mb < 4; ++mb) {
                mma16816(acc2[mb][2 * p2],     A2L[mb], BHf[0], BHf[2]);
                mma16816(acc2[mb][2 * p2 + 1], A2L[mb], BHf[1], BHf[3]);
            }
#pragma unroll
            for (int mb = 0; mb < 4; ++mb) {
                mma16816(acc2[mb][2 * p2],     A2H[mb], BLf[0], BLf[2]);
                mma16816(acc2[mb][2 * p2 + 1], A2H[mb], BLf[1], BLf[3]);
            }
        }
    }

    // ---- a1 = leaky(acc2) -> exchange [c2][px] (conflict-free float2) ----
    {
        const int qr = lane >> 2, qc = lane & 3;
#pragma unroll
        for (int mb = 0; mb < 4; ++mb) {
            int px0 = pxw + mb * 16 + qr;
#pragma unroll
            for (int nb = 0; nb < 4; ++nb) {
                int c2 = nb * 4 + qc;
                ex_f2[c2 * 512 + px0]     = leaky2(make_float2(acc2[mb][nb][0], acc2[mb][nb][1]));
                ex_f2[c2 * 512 + px0 + 8] = leaky2(make_float2(acc2[mb][nb][2], acc2[mb][nb][3]));
            }
        }
    }
    __syncthreads();

    // ================= Layers 3..7: scalar, 2 px/thread =================
    float2 a1_0[16], a1_1[16];
#pragma unroll
    for (int c2 = 0; c2 < 16; ++c2) {
        a1_0[c2] = ex_f2[c2 * 512 + tid];
        a1_1[c2] = ex_f2[c2 * 512 + tid + 256];
    }

    float2 a2_0[8], a2_1[8];
    layer2px<32, 16>(s_w + W3OFF, a1_0, a1_1, a2_0, a2_1);
#pragma unroll
    for (int o = 0; o < 8; ++o) { a2_0[o] = leaky2(a2_0[o]); a2_1[o] = leaky2(a2_1[o]); }

    float2 a3_0[4], a3_1[4];
    layer2px<16, 8>(s_w + W4OFF, a2_0, a2_1, a3_0, a3_1);
#pragma unroll
    for (int o = 0; o < 4; ++o) { a3_0[o] = leaky2(a3_0[o]); a3_1[o] = leaky2(a3_1[o]); }

    float2 a4_0[2], a4_1[2];
    layer2px<8, 4>(s_w + W5OFF, a3_0, a3_1, a4_0, a4_1);
#pragma unroll
    for (int o = 0; o < 2; ++o) { a4_0[o] = leaky2(a4_0[o]); a4_1[o] = leaky2(a4_1[o]); }

    float2 a5_0[1], a5_1[1];
    layer2px<4, 2>(s_w + W6OFF, a4_0, a4_1, a5_0, a5_1);
    a5_0[0] = leaky2(a5_0[0]);
    a5_1[0] = leaky2(a5_1[0]);

    float2 w7p = s_w[W7OFF];
    out[slab + tid]       = fmaf(a5_0[0].x, w7p.x, a5_0[0].y * w7p.y);
    out[slab + tid + 256] = fmaf(a5_1[0].x, w7p.x, a5_1[0].y * w7p.y);
}

extern "C" void kernel_launch(void* const* d_in, const int* in_sizes, int n_in,
                              void* d_out, int out_size) {
    const float* x  = (const float*)d_in[0];
    const float* w1 = (const float*)d_in[1];
    const float* w2 = (const float*)d_in[2];
    const float* w3 = (const float*)d_in[3];
    const float* w4 = (const float*)d_in[4];
    const float* w5 = (const float*)d_in[5];
    const float* w6 = (const float*)d_in[6];
    const float* w7 = (const float*)d_in[7];
    float* out = (float*)d_out;

    cudaFuncSetAttribute(fused_mlp7_hmma2_kernel,
                         cudaFuncAttributeMaxDynamicSharedMemorySize, SMEM_TOTAL);
    fused_mlp7_hmma2_kernel<<<NCTAS, THREADS, SMEM_TOTAL>>>(x, w1, w2, w3, w4, w5, w6, w7, out);
}

// round 12
// speedup vs baseline: 1.2283x; 1.0424x over previous
#include <cuda_runtime.h>
#include <cuda_bf16.h>
#include <cstdint>

#define HW      65536
#define NPIX    524288
#define THREADS 512
#define PX_CTA  512
#define NCTAS   (NPIX / PX_CTA)   // 1024

// ---- dynamic smem byte layout ----
#define SW_OFF  0          // float2[341] pair-packed w3..w7 = 2728 -> pad 2752
#define B1_OFF  2752       // w1 bf16 hi/lo: 2 * 64*272 = 34816 -> ends 37568
#define B2_OFF  37568      // w2 bf16 hi/lo: 2 * 32*144 = 9216  -> ends 46784
#define EX_OFF  46784      // a1 exchange [c2][px]: 16 * 512 * 8 = 65536 -> ends 112320
#define SMEM_TOTAL 112320

#define B1_PITCH 272
#define B1_SPLIT 17408     // 64*272
#define B2_PITCH 144
#define B2_SPLIT 4608      // 32*144

// pair-packed weight offsets inside s_w (float2 units)
#define W3OFF 0            // 32c x 8  = 256
#define W4OFF 256          // 16c x 4  = 64
#define W5OFF 320          // 8c  x 2  = 16
#define W6OFF 336          // 4c  x 1  = 4
#define W7OFF 340

__device__ __forceinline__ uint32_t smem_u32(const void* p) {
    uint32_t a;
    asm("{ .reg .u64 t; cvta.to.shared.u64 t, %1; cvt.u32.u64 %0, t; }" : "=r"(a) : "l"(p));
    return a;
}
__device__ __forceinline__ float2 ffma2(float2 a, float2 b, float2 c) {
    unsigned long long ra = reinterpret_cast<unsigned long long&>(a);
    unsigned long long rb = reinterpret_cast<unsigned long long&>(b);
    unsigned long long rc = reinterpret_cast<unsigned long long&>(c);
    unsigned long long rd;
    asm("fma.rn.f32x2 %0, %1, %2, %3;" : "=l"(rd) : "l"(ra), "l"(rb), "l"(rc));
    return reinterpret_cast<float2&>(rd);
}
__device__ __forceinline__ float2 leaky2(float2 v) {
    v.x = fmaxf(v.x, 0.01f * v.x);
    v.y = fmaxf(v.y, 0.01f * v.y);
    return v;
}
__device__ __forceinline__ void ldmx4(uint32_t* r, uint32_t addr) {
    asm volatile("ldmatrix.sync.aligned.m8n8.x4.shared.b16 {%0,%1,%2,%3}, [%4];"
                 : "=r"(r[0]), "=r"(r[1]), "=r"(r[2]), "=r"(r[3]) : "r"(addr));
}
__device__ __forceinline__ void mma16816(float* d, const uint32_t* a, uint32_t b0, uint32_t b1) {
    asm volatile("mma.sync.aligned.m16n8k16.row.col.f32.bf16.bf16.f32 "
                 "{%0,%1,%2,%3}, {%4,%5,%6,%7}, {%8,%9}, {%0,%1,%2,%3};"
                 : "+f"(d[0]), "+f"(d[1]), "+f"(d[2]), "+f"(d[3])
                 : "r"(a[0]), "r"(a[1]), "r"(a[2]), "r"(a[3]), "r"(b0), "r"(b1));
}
__device__ __forceinline__ void cvt_hilo(float a, float b, uint32_t& hi, uint32_t& lo) {
    __nv_bfloat162 h2 = __floats2bfloat162_rn(a, b);
    float2 hf = __bfloat1622float2(h2);
    __nv_bfloat162 l2 = __floats2bfloat162_rn(a - hf.x, b - hf.y);
    hi = reinterpret_cast<uint32_t&>(h2);
    lo = reinterpret_cast<uint32_t&>(l2);
}

__device__ __forceinline__ void stage_pairs(float2* dst, const float* __restrict__ w,
                                            int cout, int cin, int tid) {
    int npair = (cout / 2) * cin;
    for (int i = tid; i < npair; i += THREADS) {
        int o2 = i / cin;
        int c  = i - o2 * cin;
        dst[c * (cout / 2) + o2] = make_float2(w[(2 * o2) * cin + c], w[(2 * o2 + 1) * cin + c]);
    }
}

// stage weight [cout][cin] as bf16 hi/lo rows with given pitch/split
__device__ __forceinline__ void stage_bf16(char* base, uint32_t pitch, uint32_t split,
                                           const float* __restrict__ w, int cout, int cin, int tid) {
    for (int i = tid; i < cout * cin; i += THREADS) {
        int o = i / cin, c = i - o * cin;
        float f = w[i];
        __nv_bfloat16 h = __float2bfloat16_rn(f);
        __nv_bfloat16 l = __float2bfloat16_rn(f - __bfloat162float(h));
        char* ad = base + o * pitch + c * 2;
        *reinterpret_cast<uint16_t*>(ad)         = reinterpret_cast<uint16_t&>(h);
        *reinterpret_cast<uint16_t*>(ad + split) = reinterpret_cast<uint16_t&>(l);
    }
}

// Scalar layer for ONE pixel, channel-pair packed (R3-proven math).
template <int CIN, int COUT>
__device__ __forceinline__ void layerv(const float2* __restrict__ sw, const float2* in, float2* outv) {
    constexpr int O2 = COUT / 2;
#pragma unroll
    for (int o = 0; o < O2; ++o) outv[o] = make_float2(0.f, 0.f);
#pragma unroll
    for (int c2 = 0; c2 < CIN / 2; ++c2) {
        float2 v = in[c2];
#pragma unroll
        for (int h = 0; h < 2; ++h) {
            float s = h ? v.y : v.x;
            float2 d = make_float2(s, s);
            const float2* wr = sw + (2 * c2 + h) * O2;
            if constexpr ((O2 & 1) == 0) {
                const float4* w4 = reinterpret_cast<const float4*>(wr);
#pragma unroll
                for (int o4 = 0; o4 < O2 / 2; ++o4) {
                    float4 wp = w4[o4];
                    outv[2 * o4]     = ffma2(d, make_float2(wp.x, wp.y), outv[2 * o4]);
                    outv[2 * o4 + 1] = ffma2(d, make_float2(wp.z, wp.w), outv[2 * o4 + 1]);
                }
            } else {
#pragma unroll
                for (int o = 0; o < O2; ++o) outv[o] = ffma2(d, wr[o], outv[o]);
            }
        }
    }
}

__global__ __launch_bounds__(THREADS, 1)
void fused_mlp7_hmma3_kernel(const float* __restrict__ x,
                             const float* __restrict__ w1, const float* __restrict__ w2,
                             const float* __restrict__ w3, const float* __restrict__ w4,
                             const float* __restrict__ w5, const float* __restrict__ w6,
                             const float* __restrict__ w7,
                             float* __restrict__ out) {
    extern __shared__ char sm[];
    float2* s_w   = reinterpret_cast<float2*>(sm + SW_OFF);
    float2* ex_f2 = reinterpret_cast<float2*>(sm + EX_OFF);

    const int tid  = threadIdx.x;
    const int lane = tid & 31;
    const int warp = tid >> 5;          // 0..15

    const uint32_t smu = smem_u32(sm);
    const uint32_t B1h = smu + B1_OFF;
    const uint32_t B2h = smu + B2_OFF;

    stage_bf16(sm + B1_OFF, B1_PITCH, B1_SPLIT, w1, 64, 128, tid);
    stage_bf16(sm + B2_OFF, B2_PITCH, B2_SPLIT, w2, 32, 64, tid);
    stage_pairs(s_w + W3OFF, w3, 16, 32, tid);
    stage_pairs(s_w + W4OFF, w4, 8, 16, tid);
    stage_pairs(s_w + W5OFF, w5, 4, 8, tid);
    stage_pairs(s_w + W6OFF, w6, 2, 4, tid);
    if (tid == 0) s_w[W7OFF] = make_float2(w7[0], w7[1]);
    __syncthreads();

    // ---- this CTA's 512-px slab (always within one image) ----
    const int slab = blockIdx.x * PX_CTA;
    const float* xb = x + (size_t)(slab >> 16) * (128 * HW) + (slab & (HW - 1));

    const int fg = lane >> 2;          // fragment row group (0..7)
    const int t2 = (lane & 3) * 2;     // fragment col pair base
    const int pxw = warp * 32;         // warp's 32-px tile
    const int lrow = (lane & 7) + ((lane >> 3) & 1) * 8;
    const int lchk = lane >> 4;

    // ================= Layer 1: MMA 32px x 64o x K128 =================
    float acc[2][8][4];
#pragma unroll
    for (int mb = 0; mb < 2; ++mb)
#pragma unroll
        for (int nb = 0; nb < 8; ++nb)
#pragma unroll
            for (int r = 0; r < 4; ++r) acc[mb][nb][r] = 0.f;

    float xr[2][8];
#define LOAD_XR(kb_)                                                              \
    do {                                                                          \
        const float* cb0 = xb + (size_t)((kb_) * 16 + t2) * HW;                   \
        const float* cb1 = cb0 + HW;                                              \
        const float* cb8 = cb0 + (size_t)8 * HW;                                  \
        const float* cb9 = cb8 + HW;                                              \
        _Pragma("unroll")                                                         \
        for (int mb = 0; mb < 2; ++mb) {                                          \
            int p0 = pxw + mb * 16 + fg;                                          \
            xr[mb][0] = cb0[p0];     xr[mb][1] = cb1[p0];                         \
            xr[mb][2] = cb0[p0 + 8]; xr[mb][3] = cb1[p0 + 8];                     \
            xr[mb][4] = cb8[p0];     xr[mb][5] = cb9[p0];                         \
            xr[mb][6] = cb8[p0 + 8]; xr[mb][7] = cb9[p0 + 8];                     \
        }                                                                         \
    } while (0)

    LOAD_XR(0);

#pragma unroll
    for (int kb = 0; kb < 8; ++kb) {
        uint32_t AH[2][4], AL[2][4];
#pragma unroll
        for (int mb = 0; mb < 2; ++mb) {
            cvt_hilo(xr[mb][0], xr[mb][1], AH[mb][0], AL[mb][0]);
            cvt_hilo(xr[mb][2], xr[mb][3], AH[mb][1], AL[mb][1]);
            cvt_hilo(xr[mb][4], xr[mb][5], AH[mb][2], AL[mb][2]);
            cvt_hilo(xr[mb][6], xr[mb][7], AH[mb][3], AL[mb][3]);
        }
        if (kb < 7) LOAD_XR(kb + 1);

#pragma unroll
        for (int p = 0; p < 4; ++p) {
            uint32_t BHf[4], BLf[4];
            uint32_t bd = B1h + (uint32_t)(p * 16 + lrow) * B1_PITCH + kb * 32 + lchk * 16;
            ldmx4(BHf, bd);
            ldmx4(BLf, bd + B1_SPLIT);
            // chain-major: long same-acc reuse distance
#pragma unroll
            for (int mb = 0; mb < 2; ++mb) {
                mma16816(acc[mb][2 * p],     AH[mb], BHf[0], BHf[2]);
                mma16816(acc[mb][2 * p + 1], AH[mb], BHf[1], BHf[3]);
            }
#pragma unroll
            for (int mb = 0; mb < 2; ++mb) {
                mma16816(acc[mb][2 * p],     AL[mb], BHf[0], BHf[2]);
                mma16816(acc[mb][2 * p + 1], AL[mb], BHf[1], BHf[3]);
            }
#pragma unroll
            for (int mb = 0; mb < 2; ++mb) {
                mma16816(acc[mb][2 * p],     AH[mb], BLf[0], BLf[2]);
                mma16816(acc[mb][2 * p + 1], AH[mb], BLf[1], BLf[3]);
            }
        }
    }
#undef LOAD_XR

    // ================= Layer 2: MMA 32px x 32o x K64, A from D fragments =================
    float acc2[2][4][4];
#pragma unroll
    for (int mb = 0; mb < 2; ++mb)
#pragma unroll
        for (int nb = 0; nb < 4; ++nb)
#pragma unroll
            for (int r = 0; r < 4; ++r) acc2[mb][nb][r] = 0.f;

#pragma unroll
    for (int kb2 = 0; kb2 < 4; ++kb2) {
        uint32_t A2H[2][4], A2L[2][4];
#pragma unroll
        for (int mb = 0; mb < 2; ++mb) {
            float2 v0 = leaky2(make_float2(acc[mb][2 * kb2][0],     acc[mb][2 * kb2][1]));
            float2 v1 = leaky2(make_float2(acc[mb][2 * kb2][2],     acc[mb][2 * kb2][3]));
            float2 v2 = leaky2(make_float2(acc[mb][2 * kb2 + 1][0], acc[mb][2 * kb2 + 1][1]));
            float2 v3 = leaky2(make_float2(acc[mb][2 * kb2 + 1][2], acc[mb][2 * kb2 + 1][3]));
            cvt_hilo(v0.x, v0.y, A2H[mb][0], A2L[mb][0]);
            cvt_hilo(v1.x, v1.y, A2H[mb][1], A2L[mb][1]);
            cvt_hilo(v2.x, v2.y, A2H[mb][2], A2L[mb][2]);
            cvt_hilo(v3.x, v3.y, A2H[mb][3], A2L[mb][3]);
        }
#pragma unroll
        for (int p2 = 0; p2 < 2; ++p2) {
            uint32_t BHf[4], BLf[4];
            uint32_t bd = B2h + (uint32_t)(p2 * 16 + lrow) * B2_PITCH + kb2 * 32 + lchk * 16;
            ldmx4(BHf, bd);
            ldmx4(BLf, bd + B2_SPLIT);
#pragma unroll
            for (int mb = 0; mb < 2; ++mb) {
                mma16816(acc2[mb][2 * p2],     A2H[mb], BHf[0], BHf[2]);
                mma16816(acc2[mb][2 * p2 + 1], A2H[mb], BHf[1], BHf[3]);
            }
#pragma unroll
            for (int mb = 0; mb < 2; ++mb) {
                mma16816(acc2[mb][2 * p2],     A2L[mb], BHf[0], BHf[2]);
                mma16816(acc2[mb][2 * p2 + 1], A2L[mb], BHf[1], BHf[3]);
            }
#pragma unroll
            for (int mb = 0; mb < 2; ++mb) {
                mma16816(acc2[mb][2 * p2],     A2H[mb], BLf[0], BLf[2]);
                mma16816(acc2[mb][2 * p2 + 1], A2H[mb], BLf[1], BLf[3]);
            }
        }
    }

    // ---- a1 = leaky(acc2) -> exchange [c2][px] (conflict-free float2) ----
    {
        const int qr = lane >> 2, qc = lane & 3;
#pragma unroll
        for (int mb = 0; mb < 2; ++mb) {
            int px0 = pxw + mb * 16 + qr;
#pragma unroll
            for (int nb = 0; nb < 4; ++nb) {
                int c2 = nb * 4 + qc;
                ex_f2[c2 * 512 + px0]     = leaky2(make_float2(acc2[mb][nb][0], acc2[mb][nb][1]));
                ex_f2[c2 * 512 + px0 + 8] = leaky2(make_float2(acc2[mb][nb][2], acc2[mb][nb][3]));
            }
        }
    }
    __syncthreads();

    // ================= Layers 3..7: scalar, 1 px/thread =================
    float2 a1[16];
#pragma unroll
    for (int c2 = 0; c2 < 16; ++c2) a1[c2] = ex_f2[c2 * 512 + tid];

    float2 a2[8];
    layerv<32, 16>(s_w + W3OFF, a1, a2);
#pragma unroll
    for (int o = 0; o < 8; ++o) a2[o] = leaky2(a2[o]);
    float2 a3[4];
    layerv<16, 8>(s_w + W4OFF, a2, a3);
#pragma unroll
    for (int o = 0; o < 4; ++o) a3[o] = leaky2(a3[o]);
    float2 a4[2];
    layerv<8, 4>(s_w + W5OFF, a3, a4);
#pragma unroll
    for (int o = 0; o < 2; ++o) a4[o] = leaky2(a4[o]);
    float2 a5[1];
    layerv<4, 2>(s_w + W6OFF, a4, a5);
    a5[0] = leaky2(a5[0]);

    float2 w7p = s_w[W7OFF];
    out[slab + tid] = fmaf(a5[0].x, w7p.x, a5[0].y * w7p.y);
}

extern "C" void kernel_launch(void* const* d_in, const int* in_sizes, int n_in,
                              void* d_out, int out_size) {
    const float* x  = (const float*)d_in[0];
    const float* w1 = (const float*)d_in[1];
    const float* w2 = (const float*)d_in[2];
    const float* w3 = (const float*)d_in[3];
    const float* w4 = (const float*)d_in[4];
    const float* w5 = (const float*)d_in[5];
    const float* w6 = (const float*)d_in[6];
    const float* w7 = (const float*)d_in[7];
    float* out = (float*)d_out;

    cudaFuncSetAttribute(fused_mlp7_hmma3_kernel,
                         cudaFuncAttributeMaxDynamicSharedMemorySize, SMEM_TOTAL);
    fused_mlp7_hmma3_kernel<<<NCTAS, THREADS, SMEM_TOTAL>>>(x, w1, w2, w3, w4, w5, w6, w7, out);
}

// round 13
// speedup vs baseline: 1.2602x; 1.0260x over previous
#include <cuda_runtime.h>
#include <cuda_bf16.h>
#include <cstdint>

#define HW      65536
#define NPIX    524288
#define THREADS 512
#define PX_CTA  512
#define NCTAS   (NPIX / PX_CTA)   // 1024

// ---- dynamic smem byte layout ----
#define SW_OFF  0          // float2[341] pair-packed w3..w7 = 2728 -> pad 2752
#define B1_OFF  2752       // w1 bf16 hi/lo: 2 * 64*272 = 34816 -> ends 37568
#define B2_OFF  37568      // w2 bf16 hi/lo: 2 * 32*144 = 9216  -> ends 46784
#define EX_OFF  46784      // a1 exchange [c2][px]: 16 * 512 * 8 = 65536 -> ends 112320
#define SMEM_TOTAL 112320

#define B1_PITCH 272
#define B1_SPLIT 17408     // 64*272
#define B2_PITCH 144
#define B2_SPLIT 4608      // 32*144

// pair-packed weight offsets inside s_w (float2 units)
#define W3OFF 0            // 32c x 8  = 256
#define W4OFF 256          // 16c x 4  = 64
#define W5OFF 320          // 8c  x 2  = 16
#define W6OFF 336          // 4c  x 1  = 4
#define W7OFF 340

__device__ __forceinline__ uint32_t smem_u32(const void* p) {
    uint32_t a;
    asm("{ .reg .u64 t; cvta.to.shared.u64 t, %1; cvt.u32.u64 %0, t; }" : "=r"(a) : "l"(p));
    return a;
}
__device__ __forceinline__ float2 ffma2(float2 a, float2 b, float2 c) {
    unsigned long long ra = reinterpret_cast<unsigned long long&>(a);
    unsigned long long rb = reinterpret_cast<unsigned long long&>(b);
    unsigned long long rc = reinterpret_cast<unsigned long long&>(c);
    unsigned long long rd;
    asm("fma.rn.f32x2 %0, %1, %2, %3;" : "=l"(rd) : "l"(ra), "l"(rb), "l"(rc));
    return reinterpret_cast<float2&>(rd);
}
__device__ __forceinline__ float2 leaky2(float2 v) {
    v.x = fmaxf(v.x, 0.01f * v.x);
    v.y = fmaxf(v.y, 0.01f * v.y);
    return v;
}
__device__ __forceinline__ uint32_t prmt(uint32_t a, uint32_t b, uint32_t sel) {
    uint32_t d;
    asm("prmt.b32 %0, %1, %2, %3;" : "=r"(d) : "r"(a), "r"(b), "r"(sel));
    return d;
}
__device__ __forceinline__ void ldmx4(uint32_t* r, uint32_t addr) {
    asm volatile("ldmatrix.sync.aligned.m8n8.x4.shared.b16 {%0,%1,%2,%3}, [%4];"
                 : "=r"(r[0]), "=r"(r[1]), "=r"(r[2]), "=r"(r[3]) : "r"(addr));
}
__device__ __forceinline__ void mma16816(float* d, const uint32_t* a, uint32_t b0, uint32_t b1) {
    asm volatile("mma.sync.aligned.m16n8k16.row.col.f32.bf16.bf16.f32 "
                 "{%0,%1,%2,%3}, {%4,%5,%6,%7}, {%8,%9}, {%0,%1,%2,%3};"
                 : "+f"(d[0]), "+f"(d[1]), "+f"(d[2]), "+f"(d[3])
                 : "r"(a[0]), "r"(a[1]), "r"(a[2]), "r"(a[3]), "r"(b0), "r"(b1));
}

// FAST truncation split: hi = top-16-bits (1 PRMT for the pair), lo = RN(f - hi_f32).
// 1 PRMT + 2 LOP3 + 2 FADD + 1 F2FP (vs 2 F2FP + 2 F2F slow-class before).
__device__ __forceinline__ void cvt_hilo(float f0, float f1, uint32_t& hi, uint32_t& lo) {
    uint32_t u0 = __float_as_uint(f0), u1 = __float_as_uint(f1);
    hi = prmt(u0, u1, 0x7632);
    float h0 = __uint_as_float(u0 & 0xFFFF0000u);
    float h1 = __uint_as_float(u1 & 0xFFFF0000u);
    __nv_bfloat162 l2 = __floats2bfloat162_rn(f0 - h0, f1 - h1);
    lo = reinterpret_cast<uint32_t&>(l2);
}

__device__ __forceinline__ void stage_pairs(float2* dst, const float* __restrict__ w,
                                            int cout, int cin, int tid) {
    int npair = (cout / 2) * cin;
    for (int i = tid; i < npair; i += THREADS) {
        int o2 = i / cin;
        int c  = i - o2 * cin;
        dst[c * (cout / 2) + o2] = make_float2(w[(2 * o2) * cin + c], w[(2 * o2 + 1) * cin + c]);
    }
}

// stage weight [cout][cin] as bf16 hi/lo rows (RN split — one-time cost, max precision)
__device__ __forceinline__ void stage_bf16(char* base, uint32_t pitch, uint32_t split,
                                           const float* __restrict__ w, int cout, int cin, int tid) {
    for (int i = tid; i < cout * cin; i += THREADS) {
        int o = i / cin, c = i - o * cin;
        float f = w[i];
        __nv_bfloat16 h = __float2bfloat16_rn(f);
        __nv_bfloat16 l = __float2bfloat16_rn(f - __bfloat162float(h));
        char* ad = base + o * pitch + c * 2;
        *reinterpret_cast<uint16_t*>(ad)         = reinterpret_cast<uint16_t&>(h);
        *reinterpret_cast<uint16_t*>(ad + split) = reinterpret_cast<uint16_t&>(l);
    }
}

// Scalar layer for ONE pixel, channel-pair packed (R3-proven math).
template <int CIN, int COUT>
__device__ __forceinline__ void layerv(const float2* __restrict__ sw, const float2* in, float2* outv) {
    constexpr int O2 = COUT / 2;
#pragma unroll
    for (int o = 0; o < O2; ++o) outv[o] = make_float2(0.f, 0.f);
#pragma unroll
    for (int c2 = 0; c2 < CIN / 2; ++c2) {
        float2 v = in[c2];
#pragma unroll
        for (int h = 0; h < 2; ++h) {
            float s = h ? v.y : v.x;
            float2 d = make_float2(s, s);
            const float2* wr = sw + (2 * c2 + h) * O2;
            if constexpr ((O2 & 1) == 0) {
                const float4* w4 = reinterpret_cast<const float4*>(wr);
#pragma unroll
                for (int o4 = 0; o4 < O2 / 2; ++o4) {
                    float4 wp = w4[o4];
                    outv[2 * o4]     = ffma2(d, make_float2(wp.x, wp.y), outv[2 * o4]);
                    outv[2 * o4 + 1] = ffma2(d, make_float2(wp.z, wp.w), outv[2 * o4 + 1]);
                }
            } else {
#pragma unroll
                for (int o = 0; o < O2; ++o) outv[o] = ffma2(d, wr[o], outv[o]);
            }
        }
    }
}

__global__ __launch_bounds__(THREADS, 1)
void fused_mlp7_hmma4_kernel(const float* __restrict__ x,
                             const float* __restrict__ w1, const float* __restrict__ w2,
                             const float* __restrict__ w3, const float* __restrict__ w4,
                             const float* __restrict__ w5, const float* __restrict__ w6,
                             const float* __restrict__ w7,
                             float* __restrict__ out) {
    extern __shared__ char sm[];
    float2* s_w   = reinterpret_cast<float2*>(sm + SW_OFF);
    float2* ex_f2 = reinterpret_cast<float2*>(sm + EX_OFF);

    const int tid  = threadIdx.x;
    const int lane = tid & 31;
    const int warp = tid >> 5;          // 0..15

    const uint32_t smu = smem_u32(sm);
    const uint32_t B1h = smu + B1_OFF;
    const uint32_t B2h = smu + B2_OFF;

    stage_bf16(sm + B1_OFF, B1_PITCH, B1_SPLIT, w1, 64, 128, tid);
    stage_bf16(sm + B2_OFF, B2_PITCH, B2_SPLIT, w2, 32, 64, tid);
    stage_pairs(s_w + W3OFF, w3, 16, 32, tid);
    stage_pairs(s_w + W4OFF, w4, 8, 16, tid);
    stage_pairs(s_w + W5OFF, w5, 4, 8, tid);
    stage_pairs(s_w + W6OFF, w6, 2, 4, tid);
    if (tid == 0) s_w[W7OFF] = make_float2(w7[0], w7[1]);
    __syncthreads();

    // ---- this CTA's 512-px slab (always within one image) ----
    const int slab = blockIdx.x * PX_CTA;
    const float* xb = x + (size_t)(slab >> 16) * (128 * HW) + (slab & (HW - 1));

    const int fg = lane >> 2;          // fragment row group (0..7)
    const int t2 = (lane & 3) * 2;     // fragment col pair base
    const int pxw = warp * 32;         // warp's 32-px tile
    const int lrow = (lane & 7) + ((lane >> 3) & 1) * 8;
    const int lchk = lane >> 4;

    // ================= Layer 1: MMA 32px x 64o x K128 =================
    float acc[2][8][4];
#pragma unroll
    for (int mb = 0; mb < 2; ++mb)
#pragma unroll
        for (int nb = 0; nb < 8; ++nb)
#pragma unroll
            for (int r = 0; r < 4; ++r) acc[mb][nb][r] = 0.f;

    float xr[2][8];
#define LOAD_XR(kb_)                                                              \
    do {                                                                          \
        const float* cb0 = xb + (size_t)((kb_) * 16 + t2) * HW;                   \
        const float* cb1 = cb0 + HW;                                              \
        const float* cb8 = cb0 + (size_t)8 * HW;                                  \
        const float* cb9 = cb8 + HW;                                              \
        _Pragma("unroll")                                                         \
        for (int mb = 0; mb < 2; ++mb) {                                          \
            int p0 = pxw + mb * 16 + fg;                                          \
            xr[mb][0] = cb0[p0];     xr[mb][1] = cb1[p0];                         \
            xr[mb][2] = cb0[p0 + 8]; xr[mb][3] = cb1[p0 + 8];                     \
            xr[mb][4] = cb8[p0];     xr[mb][5] = cb9[p0];                         \
            xr[mb][6] = cb8[p0 + 8]; xr[mb][7] = cb9[p0 + 8];                     \
        }                                                                         \
    } while (0)

    LOAD_XR(0);

#pragma unroll
    for (int kb = 0; kb < 8; ++kb) {
        uint32_t AH[2][4], AL[2][4];
#pragma unroll
        for (int mb = 0; mb < 2; ++mb) {
            cvt_hilo(xr[mb][0], xr[mb][1], AH[mb][0], AL[mb][0]);
            cvt_hilo(xr[mb][2], xr[mb][3], AH[mb][1], AL[mb][1]);
            cvt_hilo(xr[mb][4], xr[mb][5], AH[mb][2], AL[mb][2]);
            cvt_hilo(xr[mb][6], xr[mb][7], AH[mb][3], AL[mb][3]);
        }
        if (kb < 7) LOAD_XR(kb + 1);

#pragma unroll
        for (int p = 0; p < 4; ++p) {
            uint32_t BHf[4], BLf[4];
            uint32_t bd = B1h + (uint32_t)(p * 16 + lrow) * B1_PITCH + kb * 32 + lchk * 16;
            ldmx4(BHf, bd);
            ldmx4(BLf, bd + B1_SPLIT);
            // chain-major: long same-acc reuse distance
#pragma unroll
            for (int mb = 0; mb < 2; ++mb) {
                mma16816(acc[mb][2 * p],     AH[mb], BHf[0], BHf[2]);
                mma16816(acc[mb][2 * p + 1], AH[mb], BHf[1], BHf[3]);
            }
#pragma unroll
            for (int mb = 0; mb < 2; ++mb) {
                mma16816(acc[mb][2 * p],     AL[mb], BHf[0], BHf[2]);
                mma16816(acc[mb][2 * p + 1], AL[mb], BHf[1], BHf[3]);
            }
#pragma unroll
            for (int mb = 0; mb < 2; ++mb) {
                mma16816(acc[mb][2 * p],     AH[mb], BLf[0], BLf[2]);
                mma16816(acc[mb][2 * p + 1], AH[mb], BLf[1], BLf[3]);
            }
        }
    }
#undef LOAD_XR

    // ================= Layer 2: MMA 32px x 32o x K64, A from D fragments =================
    float acc2[2][4][4];
#pragma unroll
    for (int mb = 0; mb < 2; ++mb)
#pragma unroll
        for (int nb = 0; nb < 4; ++nb)
#pragma unroll
            for (int r = 0; r < 4; ++r) acc2[mb][nb][r] = 0.f;

#pragma unroll
    for (int kb2 = 0; kb2 < 4; ++kb2) {
        uint32_t A2H[2][4], A2L[2][4];
#pragma unroll
        for (int mb = 0; mb < 2; ++mb) {
            float2 v0 = leaky2(make_float2(acc[mb][2 * kb2][0],     acc[mb][2 * kb2][1]));
            float2 v1 = leaky2(make_float2(acc[mb][2 * kb2][2],     acc[mb][2 * kb2][3]));
            float2 v2 = leaky2(make_float2(acc[mb][2 * kb2 + 1][0], acc[mb][2 * kb2 + 1][1]));
            float2 v3 = leaky2(make_float2(acc[mb][2 * kb2 + 1][2], acc[mb][2 * kb2 + 1][3]));
            cvt_hilo(v0.x, v0.y, A2H[mb][0], A2L[mb][0]);
            cvt_hilo(v1.x, v1.y, A2H[mb][1], A2L[mb][1]);
            cvt_hilo(v2.x, v2.y, A2H[mb][2], A2L[mb][2]);
            cvt_hilo(v3.x, v3.y, A2H[mb][3], A2L[mb][3]);
        }
#pragma unroll
        for (int p2 = 0; p2 < 2; ++p2) {
            uint32_t BHf[4], BLf[4];
            uint32_t bd = B2h + (uint32_t)(p2 * 16 + lrow) * B2_PITCH + kb2 * 32 + lchk * 16;
            ldmx4(BHf, bd);
            ldmx4(BLf, bd + B2_SPLIT);
#pragma unroll
            for (int mb = 0; mb < 2; ++mb) {
                mma16816(acc2[mb][2 * p2],     A2H[mb], BHf[0], BHf[2]);
                mma16816(acc2[mb][2 * p2 + 1], A2H[mb], BHf[1], BHf[3]);
            }
#pragma unroll
            for (int mb = 0; mb < 2; ++mb) {
                mma16816(acc2[mb][2 * p2],     A2L[mb], BHf[0], BHf[2]);
                mma16816(acc2[mb][2 * p2 + 1], A2L[mb], BHf[1], BHf[3]);
            }
#pragma unroll
            for (int mb = 0; mb < 2; ++mb) {
                mma16816(acc2[mb][2 * p2],     A2H[mb], BLf[0], BLf[2]);
                mma16816(acc2[mb][2 * p2 + 1], A2H[mb], BLf[1], BLf[3]);
            }
        }
    }

    // ---- a1 = leaky(acc2) -> exchange [c2][px] (conflict-free float2) ----
    {
        const int qr = lane >> 2, qc = lane & 3;
#pragma unroll
        for (int mb = 0; mb < 2; ++mb) {
            int px0 = pxw + mb * 16 + qr;
#pragma unroll
            for (int nb = 0; nb < 4; ++nb) {
                int c2 = nb * 4 + qc;
                ex_f2[c2 * 512 + px0]     = leaky2(make_float2(acc2[mb][nb][0], acc2[mb][nb][1]));
                ex_f2[c2 * 512 + px0 + 8] = leaky2(make_float2(acc2[mb][nb][2], acc2[mb][nb][3]));
            }
        }
    }
    __syncthreads();

    // ================= Layers 3..7: scalar, 1 px/thread =================
    float2 a1[16];
#pragma unroll
    for (int c2 = 0; c2 < 16; ++c2) a1[c2] = ex_f2[c2 * 512 + tid];

    float2 a2[8];
    layerv<32, 16>(s_w + W3OFF, a1, a2);
#pragma unroll
    for (int o = 0; o < 8; ++o) a2[o] = leaky2(a2[o]);
    float2 a3[4];
    layerv<16, 8>(s_w + W4OFF, a2, a3);
#pragma unroll
    for (int o = 0; o < 4; ++o) a3[o] = leaky2(a3[o]);
    float2 a4[2];
    layerv<8, 4>(s_w + W5OFF, a3, a4);
#pragma unroll
    for (int o = 0; o < 2; ++o) a4[o] = leaky2(a4[o]);
    float2 a5[1];
    layerv<4, 2>(s_w + W6OFF, a4, a5);
    a5[0] = leaky2(a5[0]);

    float2 w7p = s_w[W7OFF];
    out[slab + tid] = fmaf(a5[0].x, w7p.x, a5[0].y * w7p.y);
}

extern "C" void kernel_launch(void* const* d_in, const int* in_sizes, int n_in,
                              void* d_out, int out_size) {
    const float* x  = (const float*)d_in[0];
    const float* w1 = (const float*)d_in[1];
    const float* w2 = (const float*)d_in[2];
    const float* w3 = (const float*)d_in[3];
    const float* w4 = (const float*)d_in[4];
    const float* w5 = (const float*)d_in[5];
    const float* w6 = (const float*)d_in[6];
    const float* w7 = (const float*)d_in[7];
    float* out = (float*)d_out;

    cudaFuncSetAttribute(fused_mlp7_hmma4_kernel,
                         cudaFuncAttributeMaxDynamicSharedMemorySize, SMEM_TOTAL);
    fused_mlp7_hmma4_kernel<<<NCTAS, THREADS, SMEM_TOTAL>>>(x, w1, w2, w3, w4, w5, w6, w7, out);
}

// round 14
// speedup vs baseline: 1.4598x; 1.1584x over previous
#include <cuda_runtime.h>
#include <cuda_fp16.h>
#include <cstdint>

#define HW      65536
#define NPIX    524288
#define THREADS 512
#define PX_CTA  512
#define NCTAS   (NPIX / PX_CTA)   // 1024

// ---- dynamic smem byte layout ----
#define SW_OFF  0          // float2[341] pair-packed w3..w7 = 2728 -> pad 2752
#define B1_OFF  2752       // w1 fp16 (single): 64*272 = 17408 -> ends 20160
#define B2_OFF  20160      // w2 fp16 (single): 32*144 = 4608  -> ends 24768
#define EX_OFF  24768      // a1 exchange [c2][px]: 16 * 512 * 8 = 65536 -> ends 90304
#define SMEM_TOTAL 90304

#define B1_PITCH 272
#define B2_PITCH 144

// pair-packed weight offsets inside s_w (float2 units)
#define W3OFF 0            // 32c x 8  = 256
#define W4OFF 256          // 16c x 4  = 64
#define W5OFF 320          // 8c  x 2  = 16
#define W6OFF 336          // 4c  x 1  = 4
#define W7OFF 340

__device__ __forceinline__ uint32_t smem_u32(const void* p) {
    uint32_t a;
    asm("{ .reg .u64 t; cvta.to.shared.u64 t, %1; cvt.u32.u64 %0, t; }" : "=r"(a) : "l"(p));
    return a;
}
__device__ __forceinline__ float2 ffma2(float2 a, float2 b, float2 c) {
    unsigned long long ra = reinterpret_cast<unsigned long long&>(a);
    unsigned long long rb = reinterpret_cast<unsigned long long&>(b);
    unsigned long long rc = reinterpret_cast<unsigned long long&>(c);
    unsigned long long rd;
    asm("fma.rn.f32x2 %0, %1, %2, %3;" : "=l"(rd) : "l"(ra), "l"(rb), "l"(rc));
    return reinterpret_cast<float2&>(rd);
}
__device__ __forceinline__ float2 leaky2(float2 v) {
    v.x = fmaxf(v.x, 0.01f * v.x);
    v.y = fmaxf(v.y, 0.01f * v.y);
    return v;
}
__device__ __forceinline__ void ldmx4(uint32_t* r, uint32_t addr) {
    asm volatile("ldmatrix.sync.aligned.m8n8.x4.shared.b16 {%0,%1,%2,%3}, [%4];"
                 : "=r"(r[0]), "=r"(r[1]), "=r"(r[2]), "=r"(r[3]) : "r"(addr));
}
// fp16 MMA: D(f32) += A(f16) * B(f16)
__device__ __forceinline__ void mma16816(float* d, const uint32_t* a, uint32_t b0, uint32_t b1) {
    asm volatile("mma.sync.aligned.m16n8k16.row.col.f32.f16.f16.f32 "
                 "{%0,%1,%2,%3}, {%4,%5,%6,%7}, {%8,%9}, {%0,%1,%2,%3};"
                 : "+f"(d[0]), "+f"(d[1]), "+f"(d[2]), "+f"(d[3])
                 : "r"(a[0]), "r"(a[1]), "r"(a[2]), "r"(a[3]), "r"(b0), "r"(b1));
}

// fp16 A-split: hi = f32 truncated to 10 mantissa bits (exact under F2FP pack),
// lo = RN(f - hi). Per pair: 2 LOP3 + 2 FADD + 2 F2FP — no slow F2F/H2F.
// Reconstruction A = hi + lo exact to ~2^-21; B (fp16-RN) carries ~2^-12 error.
__device__ __forceinline__ void cvt_hilo(float f0, float f1, uint32_t& hi, uint32_t& lo) {
    float h0 = __uint_as_float(__float_as_uint(f0) & 0xFFFFE000u);
    float h1 = __uint_as_float(__float_as_uint(f1) & 0xFFFFE000u);
    __half2 hh = __floats2half2_rn(h0, h1);          // exact pack
    __half2 ll = __floats2half2_rn(f0 - h0, f1 - h1);
    hi = reinterpret_cast<uint32_t&>(hh);
    lo = reinterpret_cast<uint32_t&>(ll);
}

__device__ __forceinline__ void stage_pairs(float2* dst, const float* __restrict__ w,
                                            int cout, int cin, int tid) {
    int npair = (cout / 2) * cin;
    for (int i = tid; i < npair; i += THREADS) {
        int o2 = i / cin;
        int c  = i - o2 * cin;
        dst[c * (cout / 2) + o2] = make_float2(w[(2 * o2) * cin + c], w[(2 * o2 + 1) * cin + c]);
    }
}

// stage weight [cout][cin] as SINGLE fp16 RN rows (error ~2^-12, no lo plane)
__device__ __forceinline__ void stage_fp16(char* base, uint32_t pitch,
                                           const float* __restrict__ w, int cout, int cin, int tid) {
    for (int i = tid; i < cout * cin; i += THREADS) {
        int o = i / cin, c = i - o * cin;
        __half h = __float2half_rn(w[i]);
        *reinterpret_cast<uint16_t*>(base + o * pitch + c * 2) = reinterpret_cast<uint16_t&>(h);
    }
}

// Scalar layer for ONE pixel, channel-pair packed (R3-proven math).
template <int CIN, int COUT>
__device__ __forceinline__ void layerv(const float2* __restrict__ sw, const float2* in, float2* outv) {
    constexpr int O2 = COUT / 2;
#pragma unroll
    for (int o = 0; o < O2; ++o) outv[o] = make_float2(0.f, 0.f);
#pragma unroll
    for (int c2 = 0; c2 < CIN / 2; ++c2) {
        float2 v = in[c2];
#pragma unroll
        for (int h = 0; h < 2; ++h) {
            float s = h ? v.y : v.x;
            float2 d = make_float2(s, s);
            const float2* wr = sw + (2 * c2 + h) * O2;
            if constexpr ((O2 & 1) == 0) {
                const float4* w4 = reinterpret_cast<const float4*>(wr);
#pragma unroll
                for (int o4 = 0; o4 < O2 / 2; ++o4) {
                    float4 wp = w4[o4];
                    outv[2 * o4]     = ffma2(d, make_float2(wp.x, wp.y), outv[2 * o4]);
                    outv[2 * o4 + 1] = ffma2(d, make_float2(wp.z, wp.w), outv[2 * o4 + 1]);
                }
            } else {
#pragma unroll
                for (int o = 0; o < O2; ++o) outv[o] = ffma2(d, wr[o], outv[o]);
            }
        }
    }
}

__global__ __launch_bounds__(THREADS, 1)
void fused_mlp7_hmma5_kernel(const float* __restrict__ x,
                             const float* __restrict__ w1, const float* __restrict__ w2,
                             const float* __restrict__ w3, const float* __restrict__ w4,
                             const float* __restrict__ w5, const float* __restrict__ w6,
                             const float* __restrict__ w7,
                             float* __restrict__ out) {
    extern __shared__ char sm[];
    float2* s_w   = reinterpret_cast<float2*>(sm + SW_OFF);
    float2* ex_f2 = reinterpret_cast<float2*>(sm + EX_OFF);

    const int tid  = threadIdx.x;
    const int lane = tid & 31;
    const int warp = tid >> 5;          // 0..15

    const uint32_t smu = smem_u32(sm);
    const uint32_t B1h = smu + B1_OFF;
    const uint32_t B2h = smu + B2_OFF;

    stage_fp16(sm + B1_OFF, B1_PITCH, w1, 64, 128, tid);
    stage_fp16(sm + B2_OFF, B2_PITCH, w2, 32, 64, tid);
    stage_pairs(s_w + W3OFF, w3, 16, 32, tid);
    stage_pairs(s_w + W4OFF, w4, 8, 16, tid);
    stage_pairs(s_w + W5OFF, w5, 4, 8, tid);
    stage_pairs(s_w + W6OFF, w6, 2, 4, tid);
    if (tid == 0) s_w[W7OFF] = make_float2(w7[0], w7[1]);
    __syncthreads();

    // ---- this CTA's 512-px slab (always within one image) ----
    const int slab = blockIdx.x * PX_CTA;
    const float* xb = x + (size_t)(slab >> 16) * (128 * HW) + (slab & (HW - 1));

    const int fg = lane >> 2;          // fragment row group (0..7)
    const int t2 = (lane & 3) * 2;     // fragment col pair base
    const int pxw = warp * 32;         // warp's 32-px tile
    const int lrow = (lane & 7) + ((lane >> 3) & 1) * 8;
    const int lchk = lane >> 4;

    // ================= Layer 1: MMA 32px x 64o x K128, 2 chains =================
    float acc[2][8][4];
#pragma unroll
    for (int mb = 0; mb < 2; ++mb)
#pragma unroll
        for (int nb = 0; nb < 8; ++nb)
#pragma unroll
            for (int r = 0; r < 4; ++r) acc[mb][nb][r] = 0.f;

    float xr[2][8];
#define LOAD_XR(kb_)                                                              \
    do {                                                                          \
        const float* cb0 = xb + (size_t)((kb_) * 16 + t2) * HW;                   \
        const float* cb1 = cb0 + HW;                                              \
        const float* cb8 = cb0 + (size_t)8 * HW;                                  \
        const float* cb9 = cb8 + HW;                                              \
        _Pragma("unroll")                                                         \
        for (int mb = 0; mb < 2; ++mb) {                                          \
            int p0 = pxw + mb * 16 + fg;                                          \
            xr[mb][0] = cb0[p0];     xr[mb][1] = cb1[p0];                         \
            xr[mb][2] = cb0[p0 + 8]; xr[mb][3] = cb1[p0 + 8];                     \
            xr[mb][4] = cb8[p0];     xr[mb][5] = cb9[p0];                         \
            xr[mb][6] = cb8[p0 + 8]; xr[mb][7] = cb9[p0 + 8];                     \
        }                                                                         \
    } while (0)

    LOAD_XR(0);

#pragma unroll
    for (int kb = 0; kb < 8; ++kb) {
        uint32_t AH[2][4], AL[2][4];
#pragma unroll
        for (int mb = 0; mb < 2; ++mb) {
            cvt_hilo(xr[mb][0], xr[mb][1], AH[mb][0], AL[mb][0]);
            cvt_hilo(xr[mb][2], xr[mb][3], AH[mb][1], AL[mb][1]);
            cvt_hilo(xr[mb][4], xr[mb][5], AH[mb][2], AL[mb][2]);
            cvt_hilo(xr[mb][6], xr[mb][7], AH[mb][3], AL[mb][3]);
        }
        if (kb < 7) LOAD_XR(kb + 1);

#pragma unroll
        for (int p = 0; p < 4; ++p) {
            uint32_t BHf[4];
            uint32_t bd = B1h + (uint32_t)(p * 16 + lrow) * B1_PITCH + kb * 32 + lchk * 16;
            ldmx4(BHf, bd);
            // 2 chains: AhiB, AloB (chain-major for long acc reuse distance)
#pragma unroll
            for (int mb = 0; mb < 2; ++mb) {
                mma16816(acc[mb][2 * p],     AH[mb], BHf[0], BHf[2]);
                mma16816(acc[mb][2 * p + 1], AH[mb], BHf[1], BHf[3]);
            }
#pragma unroll
            for (int mb = 0; mb < 2; ++mb) {
                mma16816(acc[mb][2 * p],     AL[mb], BHf[0], BHf[2]);
                mma16816(acc[mb][2 * p + 1], AL[mb], BHf[1], BHf[3]);
            }
        }
    }
#undef LOAD_XR

    // ================= Layer 2: MMA 32px x 32o x K64, A from D fragments, 2 chains =================
    float acc2[2][4][4];
#pragma unroll
    for (int mb = 0; mb < 2; ++mb)
#pragma unroll
        for (int nb = 0; nb < 4; ++nb)
#pragma unroll
            for (int r = 0; r < 4; ++r) acc2[mb][nb][r] = 0.f;

#pragma unroll
    for (int kb2 = 0; kb2 < 4; ++kb2) {
        uint32_t A2H[2][4], A2L[2][4];
#pragma unroll
        for (int mb = 0; mb < 2; ++mb) {
            float2 v0 = leaky2(make_float2(acc[mb][2 * kb2][0],     acc[mb][2 * kb2][1]));
            float2 v1 = leaky2(make_float2(acc[mb][2 * kb2][2],     acc[mb][2 * kb2][3]));
            float2 v2 = leaky2(make_float2(acc[mb][2 * kb2 + 1][0], acc[mb][2 * kb2 + 1][1]));
            float2 v3 = leaky2(make_float2(acc[mb][2 * kb2 + 1][2], acc[mb][2 * kb2 + 1][3]));
            cvt_hilo(v0.x, v0.y, A2H[mb][0], A2L[mb][0]);
            cvt_hilo(v1.x, v1.y, A2H[mb][1], A2L[mb][1]);
            cvt_hilo(v2.x, v2.y, A2H[mb][2], A2L[mb][2]);
            cvt_hilo(v3.x, v3.y, A2H[mb][3], A2L[mb][3]);
        }
#pragma unroll
        for (int p2 = 0; p2 < 2; ++p2) {
            uint32_t BHf[4];
            uint32_t bd = B2h + (uint32_t)(p2 * 16 + lrow) * B2_PITCH + kb2 * 32 + lchk * 16;
            ldmx4(BHf, bd);
#pragma unroll
            for (int mb = 0; mb < 2; ++mb) {
                mma16816(acc2[mb][2 * p2],     A2H[mb], BHf[0], BHf[2]);
                mma16816(acc2[mb][2 * p2 + 1], A2H[mb], BHf[1], BHf[3]);
            }
#pragma unroll
            for (int mb = 0; mb < 2; ++mb) {
                mma16816(acc2[mb][2 * p2],     A2L[mb], BHf[0], BHf[2]);
                mma16816(acc2[mb][2 * p2 + 1], A2L[mb], BHf[1], BHf[3]);
            }
        }
    }

    // ---- a1 = leaky(acc2) -> exchange [c2][px] (conflict-free float2) ----
    {
        const int qr = lane >> 2, qc = lane & 3;
#pragma unroll
        for (int mb = 0; mb < 2; ++mb) {
            int px0 = pxw + mb * 16 + qr;
#pragma unroll
            for (int nb = 0; nb < 4; ++nb) {
                int c2 = nb * 4 + qc;
                ex_f2[c2 * 512 + px0]     = leaky2(make_float2(acc2[mb][nb][0], acc2[mb][nb][1]));
                ex_f2[c2 * 512 + px0 + 8] = leaky2(make_float2(acc2[mb][nb][2], acc2[mb][nb][3]));
            }
        }
    }
    __syncthreads();

    // ================= Layers 3..7: scalar, 1 px/thread =================
    float2 a1[16];
#pragma unroll
    for (int c2 = 0; c2 < 16; ++c2) a1[c2] = ex_f2[c2 * 512 + tid];

    float2 a2[8];
    layerv<32, 16>(s_w + W3OFF, a1, a2);
#pragma unroll
    for (int o = 0; o < 8; ++o) a2[o] = leaky2(a2[o]);
    float2 a3[4];
    layerv<16, 8>(s_w + W4OFF, a2, a3);
#pragma unroll
    for (int o = 0; o < 4; ++o) a3[o] = leaky2(a3[o]);
    float2 a4[2];
    layerv<8, 4>(s_w + W5OFF, a3, a4);
#pragma unroll
    for (int o = 0; o < 2; ++o) a4[o] = leaky2(a4[o]);
    float2 a5[1];
    layerv<4, 2>(s_w + W6OFF, a4, a5);
    a5[0] = leaky2(a5[0]);

    float2 w7p = s_w[W7OFF];
    out[slab + tid] = fmaf(a5[0].x, w7p.x, a5[0].y * w7p.y);
}

extern "C" void kernel_launch(void* const* d_in, const int* in_sizes, int n_in,
                              void* d_out, int out_size) {
    const float* x  = (const float*)d_in[0];
    const float* w1 = (const float*)d_in[1];
    const float* w2 = (const float*)d_in[2];
    const float* w3 = (const float*)d_in[3];
    const float* w4 = (const float*)d_in[4];
    const float* w5 = (const float*)d_in[5];
    const float* w6 = (const float*)d_in[6];
    const float* w7 = (const float*)d_in[7];
    float* out = (float*)d_out;

    cudaFuncSetAttribute(fused_mlp7_hmma5_kernel,
                         cudaFuncAttributeMaxDynamicSharedMemorySize, SMEM_TOTAL);
    fused_mlp7_hmma5_kernel<<<NCTAS, THREADS, SMEM_TOTAL>>>(x, w1, w2, w3, w4, w5, w6, w7, out);
}